// round 4
// baseline (speedup 1.0000x reference)
#include <cuda_runtime.h>
#include <cuda_bf16.h>
#include <cstdint>

// Problem constants (fixed by reference setup_inputs)
#define NROWS   2048
#define DIM     256
#define TTRK    256
#define QY      64
#define TQ      (TTRK * QY)          // 16384
#define NCOLS   (TQ + NROWS)         // 18432
#define TILE    128
#define KB      16
#define INV_TEMP (1.0f / 0.3f)

#define XY_COL_TILES (TQ / TILE)     // 128
#define COL_TILES    (NCOLS / TILE)  // 144
#define ROW_TILES    (NROWS / TILE)  // 16

// Per-row accumulators (device scratch; allocation-free per harness rules)
__device__ float g_xyT[NROWS];
__device__ float g_xyP[NROWS];
__device__ float g_xxT[NROWS];
__device__ float g_xxPf[NROWS];
__device__ float g_diag[NROWS];

__global__ void init_kernel() {
    int i = blockIdx.x * blockDim.x + threadIdx.x;
    if (i < NROWS) {
        g_xyT[i] = 0.f; g_xyP[i] = 0.f;
        g_xxT[i] = 0.f; g_xxPf[i] = 0.f;
        g_diag[i] = 0.f;
    }
}

// Fused GEMM + exp + masked row-reduction.
// Grid: (COL_TILES, ROW_TILES). Block: 256 threads, 8x8 micro-tile per thread.
__global__ __launch_bounds__(256, 2)
void sim_reduce_kernel(const float* __restrict__ x,
                       const int*   __restrict__ trk,
                       const float* __restrict__ y) {
    __shared__ float As[KB][TILE + 4];
    __shared__ float Bs[KB][TILE + 4];
    __shared__ int   s_rtrk[TILE];
    __shared__ int   s_ctrk[TILE];

    const int ct = blockIdx.x;
    const int rt = blockIdx.y;
    const int r0 = rt * TILE;
    const int c0 = ct * TILE;
    const bool is_xx = (ct >= XY_COL_TILES);

    // B rows: yf[c] = y + c*DIM for c < TQ, else x + (c-TQ)*DIM. Pure per tile.
    const float* Bbase = is_xx ? (x + (size_t)(c0 - TQ) * DIM)
                               : (y + (size_t)c0 * DIM);

    const int tid = threadIdx.x;
    if (tid < TILE) {
        s_rtrk[tid] = trk[r0 + tid];
        // xy column track = flat index mod T (tile(arange(T), Q) semantics)
        s_ctrk[tid] = is_xx ? trk[c0 - TQ + tid] : ((c0 + tid) & (TTRK - 1));
    }

    const int tx = tid & 15;   // column octet selector
    const int ty = tid >> 4;   // row octet selector (same ty = same half-warp)

    float acc[8][8];
#pragma unroll
    for (int i = 0; i < 8; i++)
#pragma unroll
        for (int j = 0; j < 8; j++) acc[i][j] = 0.f;

    for (int k0 = 0; k0 < DIM; k0 += KB) {
        __syncthreads();  // protect smem from previous iteration's readers
#pragma unroll
        for (int li = 0; li < 2; li++) {
            int idx = tid + li * 256;        // 0..511
            int row = idx >> 2;              // 0..127
            int kq  = (idx & 3) * 4;         // 0,4,8,12
            float4 av = *reinterpret_cast<const float4*>(
                x + (size_t)(r0 + row) * DIM + k0 + kq);
            float4 bv = *reinterpret_cast<const float4*>(
                Bbase + (size_t)row * DIM + k0 + kq);
            As[kq + 0][row] = av.x; As[kq + 1][row] = av.y;
            As[kq + 2][row] = av.z; As[kq + 3][row] = av.w;
            Bs[kq + 0][row] = bv.x; Bs[kq + 1][row] = bv.y;
            Bs[kq + 2][row] = bv.z; Bs[kq + 3][row] = bv.w;
        }
        __syncthreads();
#pragma unroll
        for (int kk = 0; kk < KB; kk++) {
            float4 a0 = *reinterpret_cast<const float4*>(&As[kk][ty * 8]);
            float4 a1 = *reinterpret_cast<const float4*>(&As[kk][ty * 8 + 4]);
            float4 b0 = *reinterpret_cast<const float4*>(&Bs[kk][tx * 8]);
            float4 b1 = *reinterpret_cast<const float4*>(&Bs[kk][tx * 8 + 4]);
            float a[8] = {a0.x, a0.y, a0.z, a0.w, a1.x, a1.y, a1.z, a1.w};
            float b[8] = {b0.x, b0.y, b0.z, b0.w, b1.x, b1.y, b1.z, b1.w};
#pragma unroll
            for (int i = 0; i < 8; i++)
#pragma unroll
                for (int j = 0; j < 8; j++)
                    acc[i][j] = fmaf(a[i], b[j], acc[i][j]);
        }
    }
    __syncthreads();  // s_ctrk/s_rtrk safely visible (covered by loop syncs too)

    // Epilogue: exp, masked sums, half-warp (16-lane) shuffle reduce, atomics.
    if (!is_xx) {
#pragma unroll
        for (int i = 0; i < 8; i++) {
            const int lr   = ty * 8 + i;
            const int rtrk = s_rtrk[lr];
            float t = 0.f, p = 0.f;
#pragma unroll
            for (int j = 0; j < 8; j++) {
                float s = __expf(acc[i][j] * INV_TEMP);
                t += s;
                if (s_ctrk[tx * 8 + j] == rtrk) p += s;
            }
#pragma unroll
            for (int m = 8; m >= 1; m >>= 1) {
                t += __shfl_xor_sync(0xffffffffu, t, m, 32);
                p += __shfl_xor_sync(0xffffffffu, p, m, 32);
            }
            if (tx == 0) {
                atomicAdd(&g_xyT[r0 + lr], t);
                atomicAdd(&g_xyP[r0 + lr], p);
            }
        }
    } else {
        const int cbase = c0 - TQ;  // global x-index of first column
#pragma unroll
        for (int i = 0; i < 8; i++) {
            const int lr   = ty * 8 + i;
            const int gr   = r0 + lr;
            const int rtrk = s_rtrk[lr];
            float t = 0.f, pf = 0.f;
#pragma unroll
            for (int j = 0; j < 8; j++) {
                float s = __expf(acc[i][j] * INV_TEMP);
                t += s;
                if (s_ctrk[tx * 8 + j] == rtrk) pf += s;
                if (cbase + tx * 8 + j == gr) g_diag[gr] = s;  // single writer
            }
#pragma unroll
            for (int m = 8; m >= 1; m >>= 1) {
                t  += __shfl_xor_sync(0xffffffffu, t,  m, 32);
                pf += __shfl_xor_sync(0xffffffffu, pf, m, 32);
            }
            if (tx == 0) {
                atomicAdd(&g_xxT[gr],  t);
                atomicAdd(&g_xxPf[gr], pf);
            }
        }
    }
}

// Per-track segment sums + loss. One block of 256 threads.
__global__ __launch_bounds__(256)
void finalize_kernel(const int* __restrict__ trk, float* __restrict__ out) {
    __shared__ float s_num[TTRK];
    __shared__ float s_den[TTRK];
    __shared__ int   s_cnt[TTRK];
    const int tid = threadIdx.x;
    s_num[tid] = 0.f; s_den[tid] = 0.f; s_cnt[tid] = 0;
    __syncthreads();

    for (int i = tid; i < NROWS; i += 256) {
        float xyT  = g_xyT[i];
        float xyP  = g_xyP[i];
        float xxT  = g_xxT[i];
        float xxPf = g_xxPf[i];
        float dg   = g_diag[i];
        float num  = xyP + 0.5f * (xxPf - dg);
        float den  = (xyT - xyP) + (xxT - xxPf);
        int t = trk[i];
        atomicAdd(&s_num[t], num);
        atomicAdd(&s_den[t], den);
        atomicAdd(&s_cnt[t], 1);
    }
    __syncthreads();

    float l = 0.f; int p = 0;
    if (s_cnt[tid] > 0) {
        float n = s_num[tid], d = s_den[tid];
        l = -logf(n / (d + n));
        p = 1;
    }
#pragma unroll
    for (int m = 16; m >= 1; m >>= 1) {
        l += __shfl_xor_sync(0xffffffffu, l, m, 32);
        p += __shfl_xor_sync(0xffffffffu, p, m, 32);
    }
    __shared__ float ls[8];
    __shared__ int   ps[8];
    if ((tid & 31) == 0) { ls[tid >> 5] = l; ps[tid >> 5] = p; }
    __syncthreads();
    if (tid == 0) {
        float L = 0.f; int P = 0;
#pragma unroll
        for (int w = 0; w < 8; w++) { L += ls[w]; P += ps[w]; }
        out[0] = L / (float)P;
    }
}

extern "C" void kernel_launch(void* const* d_in, const int* in_sizes, int n_in,
                              void* d_out, int out_size) {
    const float* x   = (const float*)d_in[0];   // [2048, 256]
    const int*   trk = (const int*)  d_in[1];   // [2048]
    const float* y   = (const float*)d_in[2];   // [256, 64, 256]
    float* out = (float*)d_out;

    init_kernel<<<(NROWS + 255) / 256, 256>>>();
    dim3 grid(COL_TILES, ROW_TILES);
    sim_reduce_kernel<<<grid, 256>>>(x, trk, y);
    finalize_kernel<<<1, 256>>>(trk, out);
}

// round 7
// speedup vs baseline: 4.1265x; 4.1265x over previous
#include <cuda_runtime.h>
#include <cuda_bf16.h>
#include <cstdint>

// ---------------- Problem constants ----------------
#define NROWS   2048
#define DIM     256
#define TTRK    256
#define QY      64
#define TQ      (TTRK * QY)          // 16384
#define NCOLS   (TQ + NROWS)         // 18432
#define EXP2C   4.80898346962988f    // (1/0.3) * log2(e)

#define TILE_M  128
#define TILE_N  128
#define NT      16                   // column tiles per CTA group
#define NGROUP  9                    // 8 xy groups + 1 xx group
#define ROW_TILES (NROWS / TILE_M)   // 16

// Padded k-major tile pitch: 264 bf16 = 528 bytes (132 words -> bank stride 4)
#define APITCH  528
#define TILEB   (128 * APITCH)       // 67584 bytes per 128x256 bf16 tile

// SMEM layout (dynamic, byte offsets)
#define SM_A    0
#define SM_B0   TILEB                // 67584
#define SM_B1   (2 * TILEB)         // 135168
#define SM_TRK  (3 * TILEB)         // 202752
#define SM_TOTAL (SM_TRK + NROWS * 4) // 210944

// Scratch (device globals; allocation-free per harness rules)
__device__ __nv_bfloat16 g_zb[(size_t)NCOLS * DIM];  // rows 0..TQ-1 = yf, TQ.. = x
__device__ float g_xyT[NROWS];
__device__ float g_xyP[NROWS];
__device__ float g_xxT[NROWS];
__device__ float g_xxPf[NROWS];
__device__ float g_diag[NROWS];

// ---------------- helpers ----------------
__device__ __forceinline__ uint32_t smem_u32(const void* p) {
    uint32_t a;
    asm("{ .reg .u64 t; cvta.to.shared.u64 t, %1; cvt.u32.u64 %0, t; }" : "=r"(a) : "l"(p));
    return a;
}
__device__ __forceinline__ uint32_t lds32(uint32_t addr) {
    uint32_t v;
    asm volatile("ld.shared.b32 %0, [%1];" : "=r"(v) : "r"(addr));
    return v;
}
__device__ __forceinline__ void cp16(uint32_t dst, const void* src) {
    asm volatile("cp.async.cg.shared.global [%0], [%1], 16;" :: "r"(dst), "l"(src) : "memory");
}
#define CP_COMMIT() asm volatile("cp.async.commit_group;" ::: "memory")

__device__ __forceinline__ void mma_bf16(float c[4], const uint32_t a[4], const uint32_t b[2]) {
    asm volatile(
        "mma.sync.aligned.m16n8k16.row.col.f32.bf16.bf16.f32 "
        "{%0,%1,%2,%3}, {%4,%5,%6,%7}, {%8,%9}, {%0,%1,%2,%3};"
        : "+f"(c[0]), "+f"(c[1]), "+f"(c[2]), "+f"(c[3])
        : "r"(a[0]), "r"(a[1]), "r"(a[2]), "r"(a[3]), "r"(b[0]), "r"(b[1]));
}
#define EX2(y, x) asm("ex2.approx.ftz.f32 %0, %1;" : "=f"(y) : "f"(x))

// ---------------- Kernel 0: fp32 -> bf16 conversion into g_zb ----------------
__global__ __launch_bounds__(256)
void convert_kernel(const float* __restrict__ x, const float* __restrict__ y) {
    size_t i = (size_t)blockIdx.x * blockDim.x + threadIdx.x;  // one 8-elem chunk
    size_t e = i * 8;
    const float* src = (e < (size_t)TQ * DIM) ? (y + e) : (x + (e - (size_t)TQ * DIM));
    float4 f0 = *reinterpret_cast<const float4*>(src);
    float4 f1 = *reinterpret_cast<const float4*>(src + 4);
    __nv_bfloat162 p0 = __floats2bfloat162_rn(f0.x, f0.y);
    __nv_bfloat162 p1 = __floats2bfloat162_rn(f0.z, f0.w);
    __nv_bfloat162 p2 = __floats2bfloat162_rn(f1.x, f1.y);
    __nv_bfloat162 p3 = __floats2bfloat162_rn(f1.z, f1.w);
    uint4 u;
    u.x = *reinterpret_cast<uint32_t*>(&p0);
    u.y = *reinterpret_cast<uint32_t*>(&p1);
    u.z = *reinterpret_cast<uint32_t*>(&p2);
    u.w = *reinterpret_cast<uint32_t*>(&p3);
    *reinterpret_cast<uint4*>(g_zb + e) = u;
}

__global__ void init_kernel() {
    int i = blockIdx.x * blockDim.x + threadIdx.x;
    if (i < NROWS) {
        g_xyT[i] = 0.f; g_xyP[i] = 0.f;
        g_xxT[i] = 0.f; g_xxPf[i] = 0.f; g_diag[i] = 0.f;
    }
}

// ---------------- Kernel 1: mma.sync GEMM + fused exp/masked-reduce epilogue ----------------
// Grid: 144 CTAs = 16 row tiles x 9 col groups. Block: 256 threads = 8 warps (2x4 M x N).
__global__ __launch_bounds__(256, 1)
void sim_kernel(const int* __restrict__ trk) {
    extern __shared__ char smem[];
    const uint32_t sb = smem_u32(smem);
    int* s_trk = reinterpret_cast<int*>(smem + SM_TRK);

    const int tid  = threadIdx.x;
    const int w    = tid >> 5;
    const int lane = tid & 31;
    const int gid  = lane >> 2;    // 0..7
    const int tig  = lane & 3;     // 0..3
    const int warp_m = w & 1;      // 0..1 (64-row halves)
    const int warp_n = w >> 1;     // 0..3 (32-col quarters)

    const int rt  = blockIdx.x & 15;
    const int g   = blockIdx.x >> 4;        // 0..8
    const int r0  = rt * TILE_M;
    const int ct0 = g * NT;                 // first global column tile
    const bool is_xx = (g == 8);

    // ---- Prologue: trk -> smem (plain), A tile + first two B tiles via cp.async ----
    for (int t = tid; t < NROWS; t += 256) s_trk[t] = trk[t];

    const __nv_bfloat16* Asrc = g_zb + (size_t)(TQ + r0) * DIM;
    for (int j = 0; j < 16; j++) {
        int idx = tid + j * 256;           // 0..4095
        int r = idx >> 5, c = idx & 31;    // 16B chunk c of row r
        cp16(sb + SM_A + r * APITCH + c * 16, Asrc + r * DIM + c * 8);
    }
    CP_COMMIT();
    {   // B tile 0 and 1
        for (int s = 0; s < 2; s++) {
            const __nv_bfloat16* Bsrc = g_zb + (size_t)(ct0 + s) * TILE_N * DIM;
            uint32_t bdst = sb + (s ? SM_B1 : SM_B0);
            for (int j = 0; j < 16; j++) {
                int idx = tid + j * 256;
                int r = idx >> 5, c = idx & 31;
                cp16(bdst + r * APITCH + c * 16, Bsrc + r * DIM + c * 8);
            }
            CP_COMMIT();
        }
    }

    // Per-thread fragment base offsets (bytes)
    uint32_t aoff[4], boff[4];
#pragma unroll
    for (int mf = 0; mf < 4; mf++)
        aoff[mf] = sb + SM_A + (uint32_t)(warp_m * 64 + mf * 16 + gid) * APITCH + tig * 4;
#pragma unroll
    for (int nf = 0; nf < 4; nf++)
        boff[nf] = (uint32_t)(warp_n * 32 + nf * 8 + gid) * APITCH + tig * 4;

    // Row metadata (8 rows owned per thread)
    int grs[4][2], rtrk[4][2];
    // (filled after first sync so s_trk is ready)

    // Cross-tile register accumulators
    float accT[4][2], accP[4][2];
#pragma unroll
    for (int mf = 0; mf < 4; mf++)
#pragma unroll
        for (int h = 0; h < 2; h++) { accT[mf][h] = 0.f; accP[mf][h] = 0.f; }

    const int cbase_thr = warp_n * 32 + 2 * tig;  // thread's first col within tile

    bool meta_done = false;

    for (int i = 0; i < NT; i++) {
        // Wait for B tile i (keep at most the next prefetch in flight)
        if (i < NT - 1) asm volatile("cp.async.wait_group 1;" ::: "memory");
        else            asm volatile("cp.async.wait_group 0;" ::: "memory");
        __syncthreads();

        if (!meta_done) {
            meta_done = true;
#pragma unroll
            for (int mf = 0; mf < 4; mf++)
#pragma unroll
                for (int h = 0; h < 2; h++) {
                    int gr = r0 + warp_m * 64 + mf * 16 + h * 8 + gid;
                    grs[mf][h] = gr;
                    rtrk[mf][h] = s_trk[gr];
                }
        }

        const uint32_t bbuf = sb + ((i & 1) ? SM_B1 : SM_B0);

        // ---- Compute 128x128 tile: per warp 64x32 via 16 k-steps ----
        float c[4][4][4];
#pragma unroll
        for (int mf = 0; mf < 4; mf++)
#pragma unroll
            for (int nf = 0; nf < 4; nf++)
#pragma unroll
                for (int e = 0; e < 4; e++) c[mf][nf][e] = 0.f;

#pragma unroll
        for (int ks = 0; ks < 16; ks++) {
            const uint32_t kb = ks * 32;  // 16 bf16 = 32 bytes per k-step
            uint32_t a[4][4], b[4][2];
#pragma unroll
            for (int mf = 0; mf < 4; mf++) {
                uint32_t base = aoff[mf] + kb;
                a[mf][0] = lds32(base);
                a[mf][1] = lds32(base + 8 * APITCH);
                a[mf][2] = lds32(base + 16);
                a[mf][3] = lds32(base + 8 * APITCH + 16);
            }
#pragma unroll
            for (int nf = 0; nf < 4; nf++) {
                uint32_t base = bbuf + boff[nf] + kb;
                b[nf][0] = lds32(base);
                b[nf][1] = lds32(base + 16);
            }
#pragma unroll
            for (int mf = 0; mf < 4; mf++)
#pragma unroll
                for (int nf = 0; nf < 4; nf++)
                    mma_bf16(c[mf][nf], a[mf], b[nf]);
        }

        // ---- Epilogue: exp + masked accumulate (registers only) ----
        const int colbase = (ct0 + i) * TILE_N + cbase_thr;
#pragma unroll
        for (int mf = 0; mf < 4; mf++)
#pragma unroll
            for (int h = 0; h < 2; h++) {
                const int rtk = rtrk[mf][h];
                const int gr  = grs[mf][h];
                float t = 0.f, p = 0.f;
#pragma unroll
                for (int nf = 0; nf < 4; nf++)
#pragma unroll
                    for (int e = 0; e < 2; e++) {
                        float v = c[mf][nf][h * 2 + e];
                        float sv; EX2(sv, v * EXP2C);
                        t += sv;
                        const int col = colbase + nf * 8 + e;
                        if (!is_xx) {
                            if ((col & (TTRK - 1)) == rtk) p += sv;
                        } else {
                            const int cx = col - TQ;
                            if (s_trk[cx] == rtk) p += sv;
                            if (cx == gr) g_diag[gr] = sv;
                        }
                    }
                accT[mf][h] += t;
                accP[mf][h] += p;
            }

        __syncthreads();  // everyone done reading B buf (i&1)
        if (i + 2 < NT) { // prefetch tile i+2 into the freed buffer
            const __nv_bfloat16* Bsrc = g_zb + (size_t)(ct0 + i + 2) * TILE_N * DIM;
            uint32_t bdst = sb + ((i & 1) ? SM_B1 : SM_B0);
            for (int j = 0; j < 16; j++) {
                int idx = tid + j * 256;
                int r = idx >> 5, cch = idx & 31;
                cp16(bdst + r * APITCH + cch * 16, Bsrc + r * DIM + cch * 8);
            }
            CP_COMMIT();
        }
    }

    // ---- Final: quad reduce (tig lanes) + one atomic per row ----
    float* dstT = is_xx ? g_xxT : g_xyT;
    float* dstP = is_xx ? g_xxPf : g_xyP;
#pragma unroll
    for (int mf = 0; mf < 4; mf++)
#pragma unroll
        for (int h = 0; h < 2; h++) {
            float t = accT[mf][h], p = accP[mf][h];
            t += __shfl_xor_sync(0xffffffffu, t, 1);
            t += __shfl_xor_sync(0xffffffffu, t, 2);
            p += __shfl_xor_sync(0xffffffffu, p, 1);
            p += __shfl_xor_sync(0xffffffffu, p, 2);
            if (tig == 0) {
                atomicAdd(&dstT[grs[mf][h]], t);
                atomicAdd(&dstP[grs[mf][h]], p);
            }
        }
}

// ---------------- Kernel 2: per-track segment sums + loss ----------------
__global__ __launch_bounds__(256)
void finalize_kernel(const int* __restrict__ trk, float* __restrict__ out) {
    __shared__ float s_num[TTRK];
    __shared__ float s_den[TTRK];
    __shared__ int   s_cnt[TTRK];
    const int tid = threadIdx.x;
    s_num[tid] = 0.f; s_den[tid] = 0.f; s_cnt[tid] = 0;
    __syncthreads();

    for (int i = tid; i < NROWS; i += 256) {
        float xyT = g_xyT[i], xyP = g_xyP[i];
        float xxT = g_xxT[i], xxPf = g_xxPf[i], dg = g_diag[i];
        float num = xyP + 0.5f * (xxPf - dg);
        float den = (xyT - xyP) + (xxT - xxPf);
        int t = trk[i];
        atomicAdd(&s_num[t], num);
        atomicAdd(&s_den[t], den);
        atomicAdd(&s_cnt[t], 1);
    }
    __syncthreads();

    float l = 0.f; int p = 0;
    if (s_cnt[tid] > 0) {
        float n = s_num[tid], d = s_den[tid];
        l = -logf(n / (d + n));
        p = 1;
    }
#pragma unroll
    for (int m = 16; m >= 1; m >>= 1) {
        l += __shfl_xor_sync(0xffffffffu, l, m, 32);
        p += __shfl_xor_sync(0xffffffffu, p, m, 32);
    }
    __shared__ float ls[8];
    __shared__ int   ps[8];
    if ((tid & 31) == 0) { ls[tid >> 5] = l; ps[tid >> 5] = p; }
    __syncthreads();
    if (tid == 0) {
        float L = 0.f; int P = 0;
#pragma unroll
        for (int wv = 0; wv < 8; wv++) { L += ls[wv]; P += ps[wv]; }
        out[0] = L / (float)P;
    }
}

extern "C" void kernel_launch(void* const* d_in, const int* in_sizes, int n_in,
                              void* d_out, int out_size) {
    const float* x   = (const float*)d_in[0];   // [2048, 256]
    const int*   trk = (const int*)  d_in[1];   // [2048]
    const float* y   = (const float*)d_in[2];   // [256, 64, 256]
    float* out = (float*)d_out;

    // Idempotent, called every launch (no static guards per harness rules).
    cudaFuncSetAttribute(sim_kernel, cudaFuncAttributeMaxDynamicSharedMemorySize, SM_TOTAL);

    init_kernel<<<(NROWS + 255) / 256, 256>>>();
    convert_kernel<<<(NCOLS * DIM / 8) / 256, 256>>>(x, y);   // 2304 blocks
    sim_kernel<<<ROW_TILES * NGROUP, 256, SM_TOTAL>>>(trk);
    finalize_kernel<<<1, 256>>>(trk, out);
}